// round 4
// baseline (speedup 1.0000x reference)
#include <cuda_runtime.h>

// Grouped 1x7 conv (NCHW, groups=2, identical weights per group) + roll(H).
// x: (1,48,56,56) f32, w: (24,96,7) f32, shift: int. out: (1,192,56,56) f32.
//
// Split-K tiling: a PAIR of adjacent lanes owns one output tile
// (8 w-outputs x 2 oc); lane kc = tid&1 accumulates ic in [12*kc, 12*kc+12),
// then a shfl.bfly(1) butterfly-add merges the halves. Lane kc writes oc-half kc.
// 75264 threads = 294 blocks x 256 -> 2 CTAs/SM, 16 warps/SM.

#define Hdim 56
#define Wdim 56
#define HW   3136
#define ICg  24
#define KW   7

typedef unsigned long long u64;

__device__ __forceinline__ u64 dup2(float v) {
    u64 d;
    asm("mov.b64 %0, {%1, %1};" : "=l"(d) : "f"(v));
    return d;
}
__device__ __forceinline__ void fma2(u64& acc, u64 a, u64 b) {
    asm("fma.rn.f32x2 %0, %1, %2, %0;" : "+l"(acc) : "l"(a), "l"(b));
}

__global__ __launch_bounds__(256, 2)
void conv1x7_k4(const float* __restrict__ x, const float* __restrict__ w,
                const int* __restrict__ shift, float* __restrict__ out)
{
    __shared__ float2 sw2[2 * ICg * KW];   // [pi][ic][kw] = (w_oc0, w_oc1)

    const int tid  = threadIdx.x;
    const int id   = blockIdx.x * 256 + tid;
    const int tile = id >> 1;              // output tile index
    const int kc   = id & 1;               // ic-half: 0 -> ic 0..11, 1 -> 12..23

    // first combined channel (c = g*48 + ocp) touched by this block:
    // tiles per c = 56*7 = 392; block spans 128 tiles -> at most 2 c values.
    const int c0 = (blockIdx.x * 128) / 392;

    // Stage interleaved weight pairs for combined channels c0, c0+1.
    {
        float* swf = (float*)sw2;
        for (int i = tid; i < 672; i += 256) {
            int pi = i / 336;
            int r  = i - pi * 336;
            int ic = r / 14;
            int r2 = r - ic * 14;
            int kw = r2 >> 1;
            int j  = r2 & 1;
            int c  = min(c0 + pi, 95);
            int oc = 2 * (c % 48) + j;
            swf[i] = w[ic * 672 + oc * 7 + kw];
        }
    }
    __syncthreads();

    const int wt = tile % 7;               // w-tile 0..6 (w0 = 8*wt)
    int t = tile / 7;
    const int h = t % 56;
    const int c = t / 56;                  // 0..95
    const int g   = c / 48;
    const int ocp = c - g * 48;
    const int pi  = c - c0;                // 0 or 1

    const int w0  = wt * 8;
    const bool pLo = (wt != 0);            // f4[0] covers w0-4..w0-1
    const bool pHi = (wt != 6);            // f4[3],f4[4] cover w0+8..w0+15

    const float* xrow0 = x + (size_t)g * (ICg * HW) + h * Wdim + (w0 - 4);
    const u64*   swq   = (const u64*)(sw2 + pi * ICg * KW);

    u64 acc2[8];
    #pragma unroll
    for (int i = 0; i < 8; i++) acc2[i] = 0ull;

    const float4 z4 = make_float4(0.f, 0.f, 0.f, 0.f);
    const int icb = kc * 12;

    #pragma unroll 4
    for (int ii = 0; ii < 12; ii++) {
        const int ic = icb + ii;
        const float4* xp = (const float4*)(xrow0 + ic * HW);
        float4 v0 = pLo ? xp[0] : z4;
        float4 v1 = xp[1];
        float4 v2 = xp[2];
        float4 v3 = pHi ? xp[3] : z4;
        float4 v4 = pHi ? xp[4] : z4;

        float xv[20];
        *(float4*)(xv +  0) = v0;
        *(float4*)(xv +  4) = v1;
        *(float4*)(xv +  8) = v2;
        *(float4*)(xv + 12) = v3;
        *(float4*)(xv + 16) = v4;

        u64 wq[KW];
        #pragma unroll
        for (int k = 0; k < KW; k++) wq[k] = swq[ic * KW + k];

        u64 xd[14];
        #pragma unroll
        for (int m = 0; m < 14; m++) xd[m] = dup2(xv[m + 1]);

        #pragma unroll
        for (int i = 0; i < 8; i++) {
            #pragma unroll
            for (int k = 0; k < KW; k++) {
                fma2(acc2[i], xd[i + k], wq[k]);   // x at w0+i+k-3
            }
        }
    }

    // Unpack and butterfly-add with the partner lane (other ic-half).
    float a0[8], a1[8];
    #pragma unroll
    for (int i = 0; i < 8; i++) {
        float lo, hi;
        asm("mov.b64 {%0, %1}, %2;" : "=f"(lo), "=f"(hi) : "l"(acc2[i]));
        a0[i] = lo; a1[i] = hi;
    }
    #pragma unroll
    for (int i = 0; i < 8; i++) {
        a0[i] += __shfl_xor_sync(0xffffffffu, a0[i], 1);
        a1[i] += __shfl_xor_sync(0xffffffffu, a1[i], 1);
    }

    // roll along H
    const int s = *shift;
    int ho = (h + s) % Hdim;
    if (ho < 0) ho += Hdim;

    // Lane kc writes output channel 2*ocp + kc.
    const float* a = kc ? a1 : a0;
    float* o = out + (size_t)(g * 96 + 2 * ocp + kc) * HW + ho * Wdim + w0;
    ((float4*)o)[0] = make_float4(a[0], a[1], a[2], a[3]);
    ((float4*)o)[1] = make_float4(a[4], a[5], a[6], a[7]);
}

extern "C" void kernel_launch(void* const* d_in, const int* in_sizes, int n_in,
                              void* d_out, int out_size)
{
    const float* x     = (const float*)d_in[0];
    const float* w     = (const float*)d_in[1];
    const int*   shift = (const int*)  d_in[2];
    float*       out   = (float*)d_out;

    // 96 c * 56 h * 7 wt tiles * 2 ic-halves = 75264 threads = 294 * 256
    conv1x7_k4<<<294, 256>>>(x, w, shift, out);
}